// round 1
// baseline (speedup 1.0000x reference)
#include <cuda_runtime.h>
#include <math.h>

#define BATCHN 16
#define DMODEL 192
#define DINNER 384
#define DSTATE 16
#define DTRANK 12
#define XDBLN  44
#define HHH    48
#define WWW    48
#define LLL    2304
#define EPSF   1e-5f

// ---------------- scratch (static device globals; no allocation) ----------------
__device__ float g_h1[(size_t)BATCHN * DINNER * LLL];    // after in_proj+bn1   [b][e][l]
__device__ float g_h2[(size_t)BATCHN * DINNER * LLL];    // after dwconv+silu   [b][e][l]
__device__ float g_xc[(size_t)BATCHN * LLL * DINNER];    // x_conv transposed   [b][l][e]
__device__ float g_xdbl[(size_t)BATCHN * LLL * XDBLN];   // x_dbl (Beff folded) [b][l][j]
__device__ float g_delta[(size_t)BATCHN * LLL * DINNER]; // delta               [b][l][e]
__device__ float g_y[(size_t)BATCHN * LLL * DINNER];     // scan out (spatial)  [b][l][e]
__device__ int   g_order[LLL];

// ---------------- init: snake order ----------------
__global__ void k_init_order() {
    int t = blockIdx.x * blockDim.x + threadIdx.x;
    if (t < LLL) {
        int i = t / WWW, r = t % WWW;
        int j = (i & 1) ? (WWW - 1 - r) : r;
        g_order[t] = i * WWW + j;
    }
}

// ---------------- generic tiled SGEMM ----------------
// C[M,N] = A[M,K] * B  (BT=0: B is [K,N] row-major; BT=1: B is [N,K] row-major)
// EPI 0/2: val = acc*s + (p0[m]-p3[m])*s + p2[m],  s = p1[m]*rsqrt(p4[m]+eps)
// EPI 1  : xproj epilogue (adds dir_Bs for cols 12..27), p0 = dir_Bs
template<int BT, int EPI>
__global__ void __launch_bounds__(256) k_sgemm(
    const float* __restrict__ A, const float* __restrict__ Bp, float* __restrict__ Cp,
    int M, int N, int K,
    long long strideA, long long strideB, long long strideC,
    const float* __restrict__ p0, const float* __restrict__ p1,
    const float* __restrict__ p2, const float* __restrict__ p3,
    const float* __restrict__ p4)
{
    __shared__ float As[16][68];
    __shared__ float Bs[16][68];
    const int bn0 = blockIdx.x * 64, bm0 = blockIdx.y * 64;
    const float* Ab = A + strideA * blockIdx.z;
    const float* Bb = Bp + strideB * blockIdx.z;
    float* Cb = Cp + strideC * blockIdx.z;
    const int tx = threadIdx.x, ty = threadIdx.y;
    const int tid = ty * 16 + tx;

    float acc[4][4] = {};
    for (int k0 = 0; k0 < K; k0 += 16) {
        // A tile: (m,k) -> As[k][m], coalesced over k
        #pragma unroll
        for (int i = tid; i < 1024; i += 256) {
            int m = i >> 4, k = i & 15;
            As[k][m] = Ab[(size_t)(bm0 + m) * K + k0 + k];
        }
        // B tile -> Bs[k][n]
        if (BT) {
            #pragma unroll
            for (int i = tid; i < 1024; i += 256) {
                int n = i >> 4, k = i & 15;
                int gn = bn0 + n;
                Bs[k][n] = (gn < N) ? Bb[(size_t)gn * K + k0 + k] : 0.f;
            }
        } else {
            #pragma unroll
            for (int i = tid; i < 1024; i += 256) {
                int k = i >> 6, n = i & 63;
                Bs[k][n] = Bb[(size_t)(k0 + k) * N + bn0 + n];
            }
        }
        __syncthreads();
        #pragma unroll
        for (int kk = 0; kk < 16; kk++) {
            float a[4], b[4];
            #pragma unroll
            for (int i = 0; i < 4; i++) a[i] = As[kk][ty * 4 + i];
            #pragma unroll
            for (int j = 0; j < 4; j++) b[j] = Bs[kk][tx * 4 + j];
            #pragma unroll
            for (int i = 0; i < 4; i++)
                #pragma unroll
                for (int j = 0; j < 4; j++)
                    acc[i][j] = fmaf(a[i], b[j], acc[i][j]);
        }
        __syncthreads();
    }
    // epilogue
    #pragma unroll
    for (int i = 0; i < 4; i++) {
        int m = bm0 + ty * 4 + i;
        float sc = 1.f, bi = 0.f;
        if (EPI == 0 || EPI == 2) {
            float s = p1[m] * rsqrtf(p4[m] + EPSF);
            sc = s;
            bi = (p0[m] - p3[m]) * s + p2[m];
        }
        int l = 0, dir = 0;
        if (EPI == 1) {
            l = m % LLL;
            dir = (l == 0) ? 0 : ((l % WWW == 0) ? 4 : (((l / WWW) & 1) ? 2 : 1));
        }
        #pragma unroll
        for (int j = 0; j < 4; j++) {
            int n = bn0 + tx * 4 + j;
            if (n < N) {
                float val = acc[i][j] * sc + bi;
                if (EPI == 1) {
                    if (n >= DTRANK && n < DTRANK + DSTATE)
                        val += p0[dir * DSTATE + (n - DTRANK)];
                }
                Cb[(size_t)m * N + n] = val;
            }
        }
    }
}

// ---------------- depthwise 7x7 conv + bias + SiLU ----------------
__global__ void __launch_bounds__(384) k_dwconv(const float* __restrict__ w_dw,
                                                const float* __restrict__ b_dw)
{
    __shared__ float sh[54][54];
    int e = blockIdx.x, b = blockIdx.y;
    const float* src = g_h1 + ((size_t)b * DINNER + e) * LLL;
    int tid = threadIdx.y * 48 + threadIdx.x;
    for (int i = tid; i < 54 * 54; i += 384) {
        int r = i / 54, c = i % 54;
        int gr = r - 3, gc = c - 3;
        sh[r][c] = (gr >= 0 && gr < 48 && gc >= 0 && gc < 48) ? src[gr * 48 + gc] : 0.f;
    }
    float w[49];
    #pragma unroll
    for (int i = 0; i < 49; i++) w[i] = w_dw[e * 49 + i];
    float bias = b_dw[e];
    __syncthreads();
    float* dst = g_h2 + ((size_t)b * DINNER + e) * LLL;
    int tx = threadIdx.x;
    for (int ry = threadIdx.y; ry < 48; ry += 8) {
        float acc = bias;
        #pragma unroll
        for (int ky = 0; ky < 7; ky++)
            #pragma unroll
            for (int kx = 0; kx < 7; kx++)
                acc = fmaf(sh[ry + ky][tx + kx], w[ky * 7 + kx], acc);
        float sv = acc / (1.f + __expf(-acc));  // SiLU
        dst[ry * 48 + tx] = sv;
    }
}

// ---------------- transpose [b][e][l] -> [b][l][e] ----------------
__global__ void __launch_bounds__(256) k_transpose()
{
    __shared__ float tile[32][33];
    int b = blockIdx.z;
    int l0 = blockIdx.x * 32, e0 = blockIdx.y * 32;
    const float* src = g_h2 + (size_t)b * DINNER * LLL;
    for (int i = threadIdx.y; i < 32; i += 8)
        tile[i][threadIdx.x] = src[(size_t)(e0 + i) * LLL + l0 + threadIdx.x];
    __syncthreads();
    float* dst = g_xc + (size_t)b * LLL * DINNER;
    for (int i = threadIdx.y; i < 32; i += 8)
        dst[(size_t)(l0 + i) * DINNER + e0 + threadIdx.x] = tile[threadIdx.x][i];
}

// ---------------- delta = softplus(dtr @ w_dt^T + 2*b_dt) ----------------
__global__ void __launch_bounds__(384) k_delta(const float* __restrict__ w_dt,
                                               const float* __restrict__ b_dt)
{
    int row = blockIdx.x;           // b*L + l
    int e = threadIdx.x;
    __shared__ float sdtr[DTRANK];
    if (e < DTRANK) sdtr[e] = g_xdbl[(size_t)row * XDBLN + e];
    __syncthreads();
    float acc = 2.f * b_dt[e];
    #pragma unroll
    for (int r = 0; r < DTRANK; r++)
        acc = fmaf(sdtr[r], w_dt[e * DTRANK + r], acc);
    float d = (acc > 20.f) ? acc : log1pf(expf(acc));
    g_delta[(size_t)row * DINNER + e] = d;
}

// ---------------- selective scan ----------------
// one warp handles two (b,e) lanes; lane%16 = state index n
__global__ void __launch_bounds__(128) k_scan(const float* __restrict__ A_log,
                                              const float* __restrict__ Dp)
{
    int warp = (blockIdx.x * blockDim.x + threadIdx.x) >> 5;
    int lane = threadIdx.x & 31;
    int sub = lane >> 4, n = lane & 15;
    int b = warp / (DINNER / 2);
    int e = (warp % (DINNER / 2)) * 2 + sub;

    float Aval = -expf(A_log[e * DSTATE + n]);
    float dpe = Dp[e];

    const float* pd = g_delta + (size_t)b * LLL * DINNER + e;
    const float* pu = g_xc + (size_t)b * LLL * DINNER + e;
    const float* pB = g_xdbl + (size_t)b * LLL * XDBLN + DTRANK + n;
    const float* pC = pB + DSTATE;
    float* py = g_y + (size_t)b * LLL * DINNER + e;

    float s = 0.f;
    #pragma unroll 4
    for (int t = 0; t < LLL; ++t) {
        float dv = pd[(size_t)t * DINNER];
        int ord = __ldg(&g_order[t]);
        float uv = pu[(size_t)ord * DINNER];
        float Bv = pB[(size_t)t * XDBLN];
        float Cv = pC[(size_t)t * XDBLN];
        float dA = __expf(dv * Aval);
        s = fmaf(s, dA, dv * uv * Bv);
        float y = s * Cv;
        y += __shfl_xor_sync(0xffffffffu, y, 8);
        y += __shfl_xor_sync(0xffffffffu, y, 4);
        y += __shfl_xor_sync(0xffffffffu, y, 2);
        y += __shfl_xor_sync(0xffffffffu, y, 1);
        if (n == 0) py[(size_t)ord * DINNER] = 4.f * (y + uv * dpe);
    }
}

// ---------------- LayerNorm over E + ReLU (in place on g_y) ----------------
__global__ void __launch_bounds__(128) k_ln(const float* __restrict__ ln_g,
                                            const float* __restrict__ ln_b)
{
    int row = blockIdx.x;
    float* p = g_y + (size_t)row * DINNER;
    int t = threadIdx.x;
    float v[3];
    float s = 0.f, s2 = 0.f;
    #pragma unroll
    for (int i = 0; i < 3; i++) {
        v[i] = p[t + i * 128];
        s += v[i];
        s2 += v[i] * v[i];
    }
    #pragma unroll
    for (int o = 16; o; o >>= 1) {
        s  += __shfl_xor_sync(0xffffffffu, s, o);
        s2 += __shfl_xor_sync(0xffffffffu, s2, o);
    }
    __shared__ float sh[8];
    int w = t >> 5, ln = t & 31;
    if (ln == 0) { sh[w] = s; sh[4 + w] = s2; }
    __syncthreads();
    s  = sh[0] + sh[1] + sh[2] + sh[3];
    s2 = sh[4] + sh[5] + sh[6] + sh[7];
    float mu = s * (1.f / DINNER);
    float var = s2 * (1.f / DINNER) - mu * mu;
    float r = rsqrtf(var + EPSF);
    #pragma unroll
    for (int i = 0; i < 3; i++) {
        int idx = t + i * 128;
        float val = (v[i] - mu) * r * ln_g[idx] + ln_b[idx];
        p[idx] = fmaxf(val, 0.f);
    }
}

// ---------------- launch ----------------
extern "C" void kernel_launch(void* const* d_in, const int* in_sizes, int n_in,
                              void* d_out, int out_size)
{
    const float* x     = (const float*)d_in[0];
    const float* w_in  = (const float*)d_in[1];
    const float* b_in  = (const float*)d_in[2];
    const float* bn1_g = (const float*)d_in[3];
    const float* bn1_b = (const float*)d_in[4];
    const float* bn1_m = (const float*)d_in[5];
    const float* bn1_v = (const float*)d_in[6];
    const float* w_dw  = (const float*)d_in[7];
    const float* b_dw  = (const float*)d_in[8];
    const float* w_xproj = (const float*)d_in[9];
    const float* w_dt  = (const float*)d_in[10];
    const float* b_dt  = (const float*)d_in[11];
    const float* A_log = (const float*)d_in[12];
    const float* Dp    = (const float*)d_in[13];
    const float* dir_Bs = (const float*)d_in[14];
    const float* ln_g  = (const float*)d_in[15];
    const float* ln_b  = (const float*)d_in[16];
    const float* w_out = (const float*)d_in[17];
    const float* b_out = (const float*)d_in[18];
    const float* bn2_g = (const float*)d_in[19];
    const float* bn2_b = (const float*)d_in[20];
    const float* bn2_m = (const float*)d_in[21];
    const float* bn2_v = (const float*)d_in[22];
    float* out = (float*)d_out;

    void *ph1, *ph2, *pxc, *pxdbl, *py;
    cudaGetSymbolAddress(&ph1, g_h1);
    cudaGetSymbolAddress(&ph2, g_h2);
    cudaGetSymbolAddress(&pxc, g_xc);
    cudaGetSymbolAddress(&pxdbl, g_xdbl);
    cudaGetSymbolAddress(&py, g_y);

    k_init_order<<<(LLL + 255) / 256, 256>>>();

    // 1) in_proj + bn1:  h1[b][e][l] = bn1( w_in @ x[b] )
    {
        dim3 grid(LLL / 64, DINNER / 64, BATCHN), blk(16, 16);
        k_sgemm<0, 0><<<grid, blk>>>(
            w_in, x, (float*)ph1,
            DINNER, LLL, DMODEL,
            0LL, (long long)DMODEL * LLL, (long long)DINNER * LLL,
            b_in, bn1_g, bn1_b, bn1_m, bn1_v);
    }
    // 2) depthwise conv + SiLU
    {
        dim3 grid(DINNER, BATCHN), blk(48, 8);
        k_dwconv<<<grid, blk>>>(w_dw, b_dw);
    }
    // 3) transpose to [b][l][e]
    {
        dim3 grid(LLL / 32, DINNER / 32, BATCHN), blk(32, 8);
        k_transpose<<<grid, blk>>>();
    }
    // 4) x_proj (NT) + dir_Bs fold
    {
        dim3 grid(1, (BATCHN * LLL) / 64, 1), blk(16, 16);
        k_sgemm<1, 1><<<grid, blk>>>(
            (const float*)pxc, w_xproj, (float*)pxdbl,
            BATCHN * LLL, XDBLN, DINNER,
            0LL, 0LL, 0LL,
            dir_Bs, nullptr, nullptr, nullptr, nullptr);
    }
    // 5) delta
    k_delta<<<BATCHN * LLL, DINNER>>>(w_dt, b_dt);
    // 6) scan
    {
        int warps = BATCHN * DINNER / 2;      // 3072
        k_scan<<<warps * 32 / 128, 128>>>(A_log, Dp);
    }
    // 7) layernorm + relu
    k_ln<<<BATCHN * LLL, 128>>>(ln_g, ln_b);
    // 8) out_proj (NT) + bn2 -> d_out
    {
        dim3 grid(LLL / 64, DMODEL / 64, BATCHN), blk(16, 16);
        k_sgemm<1, 2><<<grid, blk>>>(
            w_out, (const float*)py, out,
            DMODEL, LLL, DINNER,
            0LL, (long long)LLL * DINNER, (long long)DMODEL * LLL,
            b_out, bn2_g, bn2_b, bn2_m, bn2_v);
    }
    (void)in_sizes; (void)n_in; (void)out_size;
}

// round 2
// speedup vs baseline: 1.1379x; 1.1379x over previous
#include <cuda_runtime.h>
#include <math.h>

#define BATCHN 16
#define DMODEL 192
#define DINNER 384
#define DSTATE 16
#define DTRANK 12
#define XDBLN  44
#define HHH    48
#define WWW    48
#define LLL    2304
#define EPSF   1e-5f

// ---------------- scratch (static device globals; no allocation) ----------------
__device__ float g_h1[(size_t)BATCHN * DINNER * LLL];    // after in_proj+bn1   [b][e][l]
__device__ float g_h2[(size_t)BATCHN * DINNER * LLL];    // after dwconv+silu   [b][e][l]
__device__ float g_xc[(size_t)BATCHN * LLL * DINNER];    // x_conv transposed   [b][l][e]
__device__ float g_xdbl[(size_t)BATCHN * LLL * XDBLN];   // x_dbl (Beff folded) [b][l][j]
__device__ float g_delta[(size_t)BATCHN * LLL * DINNER]; // delta               [b][l][e]
__device__ float g_y[(size_t)BATCHN * LLL * DINNER];     // scan out (spatial)  [b][l][e]
__device__ int   g_order[LLL];

// ---------------- init: snake order ----------------
__global__ void k_init_order() {
    int t = blockIdx.x * blockDim.x + threadIdx.x;
    if (t < LLL) {
        int i = t / WWW, r = t % WWW;
        int j = (i & 1) ? (WWW - 1 - r) : r;
        g_order[t] = i * WWW + j;
    }
}

// ---------------- tf32 helpers ----------------
__device__ __forceinline__ unsigned f2tf(float x) {
    unsigned u; asm("cvt.rna.tf32.f32 %0, %1;" : "=r"(u) : "f"(x)); return u;
}

// ---------------- tf32 MMA GEMM ----------------
// C[M,N] = A[M,K] * B   (BT=0: B is [K,N] row-major; BT=1: B is [N,K] row-major)
// Block tile 128x64, 256 threads (8 warps as 4m x 2n), warp tile 32x32.
// EPI 0/2: val = acc*s + (p0[m]-p3[m])*s + p2[m],  s = p1[m]*rsqrt(p4[m]+eps)
// EPI 1  : xproj epilogue (adds dir_Bs for cols 12..27), p0 = dir_Bs
template<int BT, int EPI>
__global__ void __launch_bounds__(256) k_mma(
    const float* __restrict__ A, const float* __restrict__ Bp, float* __restrict__ Cp,
    int M, int N, int K,
    long long sA, long long sB, long long sC,
    const float* __restrict__ p0, const float* __restrict__ p1,
    const float* __restrict__ p2, const float* __restrict__ p3,
    const float* __restrict__ p4)
{
    __shared__ unsigned As[16][132];   // [k][m], pad 132 -> <=2-way conflicts
    __shared__ unsigned Bs[16][72];    // [k][n], pad 72  -> conflict-free frag LDS
    const int bn0 = blockIdx.x * 64, bm0 = blockIdx.y * 128;
    const float* Ab = A + sA * blockIdx.z;
    const float* Bb = Bp + sB * blockIdx.z;
    float* Cb = Cp + sC * blockIdx.z;

    const int tid  = threadIdx.x;
    const int lane = tid & 31, wid = tid >> 5;
    const int wm = wid & 3, wn = wid >> 2;
    const int qr = lane >> 2, qc = lane & 3;

    float acc[2][4][4];
    #pragma unroll
    for (int i = 0; i < 2; i++)
        #pragma unroll
        for (int j = 0; j < 4; j++)
            #pragma unroll
            for (int r = 0; r < 4; r++) acc[i][j][r] = 0.f;

    for (int k0 = 0; k0 < K; k0 += 16) {
        // --- A tile: 128 m x 16 k, float4 along k, scatter to As[k][m]
        #pragma unroll
        for (int it = 0; it < 2; it++) {
            int idx = tid + it * 256;        // 0..511
            int m = idx >> 2, k4 = (idx & 3) << 2;
            int gm = bm0 + m;
            float4 v = make_float4(0.f, 0.f, 0.f, 0.f);
            if (gm < M) v = *(const float4*)(Ab + (size_t)gm * K + k0 + k4);
            As[k4 + 0][m] = f2tf(v.x);
            As[k4 + 1][m] = f2tf(v.y);
            As[k4 + 2][m] = f2tf(v.z);
            As[k4 + 3][m] = f2tf(v.w);
        }
        // --- B tile: 16 k x 64 n
        if (BT) {
            int n = tid >> 2, k4 = (tid & 3) << 2;
            int gn = bn0 + n;
            float4 v = make_float4(0.f, 0.f, 0.f, 0.f);
            if (gn < N) v = *(const float4*)(Bb + (size_t)gn * K + k0 + k4);
            Bs[k4 + 0][n] = f2tf(v.x);
            Bs[k4 + 1][n] = f2tf(v.y);
            Bs[k4 + 2][n] = f2tf(v.z);
            Bs[k4 + 3][n] = f2tf(v.w);
        } else {
            int k = tid >> 4, n4 = (tid & 15) << 2;
            float4 v = *(const float4*)(Bb + (size_t)(k0 + k) * N + bn0 + n4);
            uint4 u = make_uint4(f2tf(v.x), f2tf(v.y), f2tf(v.z), f2tf(v.w));
            *(uint4*)&Bs[k][n4] = u;
        }
        __syncthreads();

        #pragma unroll
        for (int kk = 0; kk < 2; kk++) {
            unsigned a[2][4], b[4][2];
            #pragma unroll
            for (int im = 0; im < 2; im++) {
                int rb = wm * 32 + im * 16 + qr;
                a[im][0] = As[kk * 8 + qc    ][rb    ];
                a[im][1] = As[kk * 8 + qc    ][rb + 8];
                a[im][2] = As[kk * 8 + qc + 4][rb    ];
                a[im][3] = As[kk * 8 + qc + 4][rb + 8];
            }
            #pragma unroll
            for (int jn = 0; jn < 4; jn++) {
                int cb = wn * 32 + jn * 8 + qr;
                b[jn][0] = Bs[kk * 8 + qc    ][cb];
                b[jn][1] = Bs[kk * 8 + qc + 4][cb];
            }
            #pragma unroll
            for (int im = 0; im < 2; im++)
                #pragma unroll
                for (int jn = 0; jn < 4; jn++)
                    asm volatile(
                        "mma.sync.aligned.m16n8k8.row.col.f32.tf32.tf32.f32 "
                        "{%0,%1,%2,%3}, {%4,%5,%6,%7}, {%8,%9}, {%0,%1,%2,%3};"
                        : "+f"(acc[im][jn][0]), "+f"(acc[im][jn][1]),
                          "+f"(acc[im][jn][2]), "+f"(acc[im][jn][3])
                        : "r"(a[im][0]), "r"(a[im][1]), "r"(a[im][2]), "r"(a[im][3]),
                          "r"(b[jn][0]), "r"(b[jn][1]));
        }
        __syncthreads();
    }

    // --- epilogue ---
    #pragma unroll
    for (int im = 0; im < 2; im++) {
        int r0 = bm0 + wm * 32 + im * 16 + qr;
        int r1 = r0 + 8;
        float s0 = 1.f, bi0 = 0.f, s1 = 1.f, bi1 = 0.f;
        int d0 = 0, d1 = 0;
        if (EPI != 1) {
            if (r0 < M) { float s = p1[r0] * rsqrtf(p4[r0] + EPSF); s0 = s; bi0 = (p0[r0] - p3[r0]) * s + p2[r0]; }
            if (r1 < M) { float s = p1[r1] * rsqrtf(p4[r1] + EPSF); s1 = s; bi1 = (p0[r1] - p3[r1]) * s + p2[r1]; }
        } else {
            int l0 = r0 % LLL; d0 = (l0 == 0) ? 0 : ((l0 % WWW == 0) ? 4 : (((l0 / WWW) & 1) ? 2 : 1));
            int l1 = r1 % LLL; d1 = (l1 == 0) ? 0 : ((l1 % WWW == 0) ? 4 : (((l1 / WWW) & 1) ? 2 : 1));
        }
        #pragma unroll
        for (int jn = 0; jn < 4; jn++) {
            int c = bn0 + wn * 32 + jn * 8 + qc * 2;
            if (EPI != 1) {
                if (c < N) {
                    if (r0 < M) {
                        float2 v = make_float2(acc[im][jn][0] * s0 + bi0, acc[im][jn][1] * s0 + bi0);
                        *(float2*)(Cb + (size_t)r0 * N + c) = v;
                    }
                    if (r1 < M) {
                        float2 v = make_float2(acc[im][jn][2] * s1 + bi1, acc[im][jn][3] * s1 + bi1);
                        *(float2*)(Cb + (size_t)r1 * N + c) = v;
                    }
                }
            } else {
                if (c < N) {
                    float v0 = acc[im][jn][0], v1 = acc[im][jn][1];
                    float v2 = acc[im][jn][2], v3 = acc[im][jn][3];
                    if (c >= DTRANK && c < DTRANK + DSTATE) {
                        v0 += p0[d0 * DSTATE + c - DTRANK];
                        v2 += p0[d1 * DSTATE + c - DTRANK];
                    }
                    if (c + 1 >= DTRANK && c + 1 < DTRANK + DSTATE) {
                        v1 += p0[d0 * DSTATE + c + 1 - DTRANK];
                        v3 += p0[d1 * DSTATE + c + 1 - DTRANK];
                    }
                    *(float2*)(Cb + (size_t)r0 * N + c) = make_float2(v0, v1);
                    *(float2*)(Cb + (size_t)r1 * N + c) = make_float2(v2, v3);
                }
            }
        }
    }
}

// ---------------- depthwise 7x7 conv + bias + SiLU ----------------
__global__ void __launch_bounds__(384) k_dwconv(const float* __restrict__ w_dw,
                                                const float* __restrict__ b_dw)
{
    __shared__ float sh[54][54];
    int e = blockIdx.x, b = blockIdx.y;
    const float* src = g_h1 + ((size_t)b * DINNER + e) * LLL;
    int tid = threadIdx.y * 48 + threadIdx.x;
    for (int i = tid; i < 54 * 54; i += 384) {
        int r = i / 54, c = i % 54;
        int gr = r - 3, gc = c - 3;
        sh[r][c] = (gr >= 0 && gr < 48 && gc >= 0 && gc < 48) ? src[gr * 48 + gc] : 0.f;
    }
    float w[49];
    #pragma unroll
    for (int i = 0; i < 49; i++) w[i] = w_dw[e * 49 + i];
    float bias = b_dw[e];
    __syncthreads();
    float* dst = g_h2 + ((size_t)b * DINNER + e) * LLL;
    int tx = threadIdx.x;
    for (int ry = threadIdx.y; ry < 48; ry += 8) {
        float acc = bias;
        #pragma unroll
        for (int ky = 0; ky < 7; ky++)
            #pragma unroll
            for (int kx = 0; kx < 7; kx++)
                acc = fmaf(sh[ry + ky][tx + kx], w[ky * 7 + kx], acc);
        float sv = acc / (1.f + __expf(-acc));  // SiLU
        dst[ry * 48 + tx] = sv;
    }
}

// ---------------- transpose [b][e][l] -> [b][l][e] ----------------
__global__ void __launch_bounds__(256) k_transpose()
{
    __shared__ float tile[32][33];
    int b = blockIdx.z;
    int l0 = blockIdx.x * 32, e0 = blockIdx.y * 32;
    const float* src = g_h2 + (size_t)b * DINNER * LLL;
    for (int i = threadIdx.y; i < 32; i += 8)
        tile[i][threadIdx.x] = src[(size_t)(e0 + i) * LLL + l0 + threadIdx.x];
    __syncthreads();
    float* dst = g_xc + (size_t)b * LLL * DINNER;
    for (int i = threadIdx.y; i < 32; i += 8)
        dst[(size_t)(l0 + i) * DINNER + e0 + threadIdx.x] = tile[threadIdx.x][i];
}

// ---------------- delta = softplus(dtr @ w_dt^T + 2*b_dt) ----------------
__global__ void __launch_bounds__(384) k_delta(const float* __restrict__ w_dt,
                                               const float* __restrict__ b_dt)
{
    int row = blockIdx.x;           // b*L + l
    int e = threadIdx.x;
    __shared__ float sdtr[DTRANK];
    if (e < DTRANK) sdtr[e] = g_xdbl[(size_t)row * XDBLN + e];
    __syncthreads();
    float acc = 2.f * b_dt[e];
    #pragma unroll
    for (int r = 0; r < DTRANK; r++)
        acc = fmaf(sdtr[r], w_dt[e * DTRANK + r], acc);
    float d = (acc > 20.f) ? acc : log1pf(expf(acc));
    g_delta[(size_t)row * DINNER + e] = d;
}

// ---------------- selective scan ----------------
// one warp handles two (b,e) lanes; lane%16 = state index n
__global__ void __launch_bounds__(128) k_scan(const float* __restrict__ A_log,
                                              const float* __restrict__ Dp)
{
    int warp = (blockIdx.x * blockDim.x + threadIdx.x) >> 5;
    int lane = threadIdx.x & 31;
    int sub = lane >> 4, n = lane & 15;
    int b = warp / (DINNER / 2);
    int e = (warp % (DINNER / 2)) * 2 + sub;

    float Aval = -expf(A_log[e * DSTATE + n]);
    float dpe = Dp[e];

    const float* pd = g_delta + (size_t)b * LLL * DINNER + e;
    const float* pu = g_xc + (size_t)b * LLL * DINNER + e;
    const float* pB = g_xdbl + (size_t)b * LLL * XDBLN + DTRANK + n;
    const float* pC = pB + DSTATE;
    float* py = g_y + (size_t)b * LLL * DINNER + e;

    float s = 0.f;
    #pragma unroll 4
    for (int t = 0; t < LLL; ++t) {
        float dv = pd[(size_t)t * DINNER];
        int ord = __ldg(&g_order[t]);
        float uv = pu[(size_t)ord * DINNER];
        float Bv = pB[(size_t)t * XDBLN];
        float Cv = pC[(size_t)t * XDBLN];
        float dA = __expf(dv * Aval);
        s = fmaf(s, dA, dv * uv * Bv);
        float y = s * Cv;
        y += __shfl_xor_sync(0xffffffffu, y, 8);
        y += __shfl_xor_sync(0xffffffffu, y, 4);
        y += __shfl_xor_sync(0xffffffffu, y, 2);
        y += __shfl_xor_sync(0xffffffffu, y, 1);
        if (n == 0) py[(size_t)ord * DINNER] = 4.f * (y + uv * dpe);
    }
}

// ---------------- LayerNorm over E + ReLU (in place on g_y) ----------------
__global__ void __launch_bounds__(128) k_ln(const float* __restrict__ ln_g,
                                            const float* __restrict__ ln_b)
{
    int row = blockIdx.x;
    float* p = g_y + (size_t)row * DINNER;
    int t = threadIdx.x;
    float v[3];
    float s = 0.f, s2 = 0.f;
    #pragma unroll
    for (int i = 0; i < 3; i++) {
        v[i] = p[t + i * 128];
        s += v[i];
        s2 += v[i] * v[i];
    }
    #pragma unroll
    for (int o = 16; o; o >>= 1) {
        s  += __shfl_xor_sync(0xffffffffu, s, o);
        s2 += __shfl_xor_sync(0xffffffffu, s2, o);
    }
    __shared__ float sh[8];
    int w = t >> 5, ln = t & 31;
    if (ln == 0) { sh[w] = s; sh[4 + w] = s2; }
    __syncthreads();
    s  = sh[0] + sh[1] + sh[2] + sh[3];
    s2 = sh[4] + sh[5] + sh[6] + sh[7];
    float mu = s * (1.f / DINNER);
    float var = s2 * (1.f / DINNER) - mu * mu;
    float r = rsqrtf(var + EPSF);
    #pragma unroll
    for (int i = 0; i < 3; i++) {
        int idx = t + i * 128;
        float val = (v[i] - mu) * r * ln_g[idx] + ln_b[idx];
        p[idx] = fmaxf(val, 0.f);
    }
}

// ---------------- launch ----------------
extern "C" void kernel_launch(void* const* d_in, const int* in_sizes, int n_in,
                              void* d_out, int out_size)
{
    const float* x     = (const float*)d_in[0];
    const float* w_in  = (const float*)d_in[1];
    const float* b_in  = (const float*)d_in[2];
    const float* bn1_g = (const float*)d_in[3];
    const float* bn1_b = (const float*)d_in[4];
    const float* bn1_m = (const float*)d_in[5];
    const float* bn1_v = (const float*)d_in[6];
    const float* w_dw  = (const float*)d_in[7];
    const float* b_dw  = (const float*)d_in[8];
    const float* w_xproj = (const float*)d_in[9];
    const float* w_dt  = (const float*)d_in[10];
    const float* b_dt  = (const float*)d_in[11];
    const float* A_log = (const float*)d_in[12];
    const float* Dp    = (const float*)d_in[13];
    const float* dir_Bs = (const float*)d_in[14];
    const float* ln_g  = (const float*)d_in[15];
    const float* ln_b  = (const float*)d_in[16];
    const float* w_out = (const float*)d_in[17];
    const float* b_out = (const float*)d_in[18];
    const float* bn2_g = (const float*)d_in[19];
    const float* bn2_b = (const float*)d_in[20];
    const float* bn2_m = (const float*)d_in[21];
    const float* bn2_v = (const float*)d_in[22];
    float* out = (float*)d_out;

    void *ph1, *pxc, *pxdbl, *py;
    cudaGetSymbolAddress(&ph1, g_h1);
    cudaGetSymbolAddress(&pxc, g_xc);
    cudaGetSymbolAddress(&pxdbl, g_xdbl);
    cudaGetSymbolAddress(&py, g_y);

    k_init_order<<<(LLL + 255) / 256, 256>>>();

    // 1) in_proj + bn1:  h1[b][e][l] = bn1( w_in @ x[b] )
    {
        dim3 grid(LLL / 64, (DINNER + 127) / 128, BATCHN), blk(256);
        k_mma<0, 0><<<grid, blk>>>(
            w_in, x, (float*)ph1,
            DINNER, LLL, DMODEL,
            0LL, (long long)DMODEL * LLL, (long long)DINNER * LLL,
            b_in, bn1_g, bn1_b, bn1_m, bn1_v);
    }
    // 2) depthwise conv + SiLU
    {
        dim3 grid(DINNER, BATCHN), blk(48, 8);
        k_dwconv<<<grid, blk>>>(w_dw, b_dw);
    }
    // 3) transpose to [b][l][e]
    {
        dim3 grid(LLL / 32, DINNER / 32, BATCHN), blk(32, 8);
        k_transpose<<<grid, blk>>>();
    }
    // 4) x_proj (NT) + dir_Bs fold
    {
        dim3 grid(1, (BATCHN * LLL) / 128, 1), blk(256);
        k_mma<1, 1><<<grid, blk>>>(
            (const float*)pxc, w_xproj, (float*)pxdbl,
            BATCHN * LLL, XDBLN, DINNER,
            0LL, 0LL, 0LL,
            dir_Bs, nullptr, nullptr, nullptr, nullptr);
    }
    // 5) delta
    k_delta<<<BATCHN * LLL, DINNER>>>(w_dt, b_dt);
    // 6) scan
    {
        int warps = BATCHN * DINNER / 2;      // 3072
        k_scan<<<warps * 32 / 128, 128>>>(A_log, Dp);
    }
    // 7) layernorm + relu
    k_ln<<<BATCHN * LLL, 128>>>(ln_g, ln_b);
    // 8) out_proj (NT) + bn2 -> d_out
    {
        dim3 grid(LLL / 64, (DMODEL + 127) / 128, BATCHN), blk(256);
        k_mma<1, 2><<<grid, blk>>>(
            w_out, (const float*)py, out,
            DMODEL, LLL, DINNER,
            0LL, (long long)LLL * DINNER, (long long)DMODEL * LLL,
            b_out, bn2_g, bn2_b, bn2_m, bn2_v);
    }
    (void)in_sizes; (void)n_in; (void)out_size;
}

// round 3
// speedup vs baseline: 1.2059x; 1.0598x over previous
#include <cuda_runtime.h>
#include <math.h>

#define BATCHN 16
#define DMODEL 192
#define DINNER 384
#define DSTATE 16
#define DTRANK 12
#define XDBLN  44
#define HHH    48
#define WWW    48
#define LLL    2304
#define EPSF   1e-5f

// ---------------- scratch (static device globals; no allocation) ----------------
__device__ float g_h1[(size_t)BATCHN * DINNER * LLL];    // after in_proj+bn1   [b][e][l]
__device__ float g_h2[(size_t)BATCHN * DINNER * LLL];    // after dwconv+silu   [b][e][l]
__device__ float g_xc[(size_t)BATCHN * LLL * DINNER];    // x_conv transposed   [b][l][e]
__device__ float g_xdbl[(size_t)BATCHN * LLL * XDBLN];   // x_dbl (Beff folded) [b][l][j]
__device__ float g_delta[(size_t)BATCHN * LLL * DINNER]; // delta               [b][l][e]
__device__ float g_y[(size_t)BATCHN * LLL * DINNER];     // scan out (spatial)  [b][l][e]
__device__ int   g_order[LLL];

// ---------------- init: snake order ----------------
__global__ void k_init_order() {
    int t = blockIdx.x * blockDim.x + threadIdx.x;
    if (t < LLL) {
        int i = t / WWW, r = t % WWW;
        int j = (i & 1) ? (WWW - 1 - r) : r;
        g_order[t] = i * WWW + j;
    }
}

// ---------------- tf32 helpers ----------------
__device__ __forceinline__ unsigned f2tf(float x) {
    unsigned u; asm("cvt.rna.tf32.f32 %0, %1;" : "=r"(u) : "f"(x)); return u;
}

// ---------------- tf32 MMA GEMM ----------------
template<int BT, int EPI>
__global__ void __launch_bounds__(256) k_mma(
    const float* __restrict__ A, const float* __restrict__ Bp, float* __restrict__ Cp,
    int M, int N, int K,
    long long sA, long long sB, long long sC,
    const float* __restrict__ p0, const float* __restrict__ p1,
    const float* __restrict__ p2, const float* __restrict__ p3,
    const float* __restrict__ p4)
{
    __shared__ unsigned As[16][132];
    __shared__ unsigned Bs[16][72];
    const int bn0 = blockIdx.x * 64, bm0 = blockIdx.y * 128;
    const float* Ab = A + sA * blockIdx.z;
    const float* Bb = Bp + sB * blockIdx.z;
    float* Cb = Cp + sC * blockIdx.z;

    const int tid  = threadIdx.x;
    const int lane = tid & 31, wid = tid >> 5;
    const int wm = wid & 3, wn = wid >> 2;
    const int qr = lane >> 2, qc = lane & 3;

    float acc[2][4][4];
    #pragma unroll
    for (int i = 0; i < 2; i++)
        #pragma unroll
        for (int j = 0; j < 4; j++)
            #pragma unroll
            for (int r = 0; r < 4; r++) acc[i][j][r] = 0.f;

    for (int k0 = 0; k0 < K; k0 += 16) {
        #pragma unroll
        for (int it = 0; it < 2; it++) {
            int idx = tid + it * 256;
            int m = idx >> 2, k4 = (idx & 3) << 2;
            int gm = bm0 + m;
            float4 v = make_float4(0.f, 0.f, 0.f, 0.f);
            if (gm < M) v = *(const float4*)(Ab + (size_t)gm * K + k0 + k4);
            As[k4 + 0][m] = f2tf(v.x);
            As[k4 + 1][m] = f2tf(v.y);
            As[k4 + 2][m] = f2tf(v.z);
            As[k4 + 3][m] = f2tf(v.w);
        }
        if (BT) {
            int n = tid >> 2, k4 = (tid & 3) << 2;
            int gn = bn0 + n;
            float4 v = make_float4(0.f, 0.f, 0.f, 0.f);
            if (gn < N) v = *(const float4*)(Bb + (size_t)gn * K + k0 + k4);
            Bs[k4 + 0][n] = f2tf(v.x);
            Bs[k4 + 1][n] = f2tf(v.y);
            Bs[k4 + 2][n] = f2tf(v.z);
            Bs[k4 + 3][n] = f2tf(v.w);
        } else {
            int k = tid >> 4, n4 = (tid & 15) << 2;
            float4 v = *(const float4*)(Bb + (size_t)(k0 + k) * N + bn0 + n4);
            uint4 u = make_uint4(f2tf(v.x), f2tf(v.y), f2tf(v.z), f2tf(v.w));
            *(uint4*)&Bs[k][n4] = u;
        }
        __syncthreads();

        #pragma unroll
        for (int kk = 0; kk < 2; kk++) {
            unsigned a[2][4], b[4][2];
            #pragma unroll
            for (int im = 0; im < 2; im++) {
                int rb = wm * 32 + im * 16 + qr;
                a[im][0] = As[kk * 8 + qc    ][rb    ];
                a[im][1] = As[kk * 8 + qc    ][rb + 8];
                a[im][2] = As[kk * 8 + qc + 4][rb    ];
                a[im][3] = As[kk * 8 + qc + 4][rb + 8];
            }
            #pragma unroll
            for (int jn = 0; jn < 4; jn++) {
                int cb = wn * 32 + jn * 8 + qr;
                b[jn][0] = Bs[kk * 8 + qc    ][cb];
                b[jn][1] = Bs[kk * 8 + qc + 4][cb];
            }
            #pragma unroll
            for (int im = 0; im < 2; im++)
                #pragma unroll
                for (int jn = 0; jn < 4; jn++)
                    asm volatile(
                        "mma.sync.aligned.m16n8k8.row.col.f32.tf32.tf32.f32 "
                        "{%0,%1,%2,%3}, {%4,%5,%6,%7}, {%8,%9}, {%0,%1,%2,%3};"
                        : "+f"(acc[im][jn][0]), "+f"(acc[im][jn][1]),
                          "+f"(acc[im][jn][2]), "+f"(acc[im][jn][3])
                        : "r"(a[im][0]), "r"(a[im][1]), "r"(a[im][2]), "r"(a[im][3]),
                          "r"(b[jn][0]), "r"(b[jn][1]));
        }
        __syncthreads();
    }

    #pragma unroll
    for (int im = 0; im < 2; im++) {
        int r0 = bm0 + wm * 32 + im * 16 + qr;
        int r1 = r0 + 8;
        float s0 = 1.f, bi0 = 0.f, s1 = 1.f, bi1 = 0.f;
        int d0 = 0, d1 = 0;
        if (EPI != 1) {
            if (r0 < M) { float s = p1[r0] * rsqrtf(p4[r0] + EPSF); s0 = s; bi0 = (p0[r0] - p3[r0]) * s + p2[r0]; }
            if (r1 < M) { float s = p1[r1] * rsqrtf(p4[r1] + EPSF); s1 = s; bi1 = (p0[r1] - p3[r1]) * s + p2[r1]; }
        } else {
            int l0 = r0 % LLL; d0 = (l0 == 0) ? 0 : ((l0 % WWW == 0) ? 4 : (((l0 / WWW) & 1) ? 2 : 1));
            int l1 = r1 % LLL; d1 = (l1 == 0) ? 0 : ((l1 % WWW == 0) ? 4 : (((l1 / WWW) & 1) ? 2 : 1));
        }
        #pragma unroll
        for (int jn = 0; jn < 4; jn++) {
            int c = bn0 + wn * 32 + jn * 8 + qc * 2;
            if (EPI != 1) {
                if (c < N) {
                    if (r0 < M) {
                        float2 v = make_float2(acc[im][jn][0] * s0 + bi0, acc[im][jn][1] * s0 + bi0);
                        *(float2*)(Cb + (size_t)r0 * N + c) = v;
                    }
                    if (r1 < M) {
                        float2 v = make_float2(acc[im][jn][2] * s1 + bi1, acc[im][jn][3] * s1 + bi1);
                        *(float2*)(Cb + (size_t)r1 * N + c) = v;
                    }
                }
            } else {
                if (c < N) {
                    float v0 = acc[im][jn][0], v1 = acc[im][jn][1];
                    float v2 = acc[im][jn][2], v3 = acc[im][jn][3];
                    if (c >= DTRANK && c < DTRANK + DSTATE) {
                        v0 += p0[d0 * DSTATE + c - DTRANK];
                        v2 += p0[d1 * DSTATE + c - DTRANK];
                    }
                    if (c + 1 >= DTRANK && c + 1 < DTRANK + DSTATE) {
                        v1 += p0[d0 * DSTATE + c + 1 - DTRANK];
                        v3 += p0[d1 * DSTATE + c + 1 - DTRANK];
                    }
                    *(float2*)(Cb + (size_t)r0 * N + c) = make_float2(v0, v1);
                    *(float2*)(Cb + (size_t)r1 * N + c) = make_float2(v2, v3);
                }
            }
        }
    }
}

// ---------------- depthwise 7x7 conv + bias + SiLU ----------------
__global__ void __launch_bounds__(384) k_dwconv(const float* __restrict__ w_dw,
                                                const float* __restrict__ b_dw)
{
    __shared__ float sh[54][54];
    int e = blockIdx.x, b = blockIdx.y;
    const float* src = g_h1 + ((size_t)b * DINNER + e) * LLL;
    int tid = threadIdx.y * 48 + threadIdx.x;
    for (int i = tid; i < 54 * 54; i += 384) {
        int r = i / 54, c = i % 54;
        int gr = r - 3, gc = c - 3;
        sh[r][c] = (gr >= 0 && gr < 48 && gc >= 0 && gc < 48) ? src[gr * 48 + gc] : 0.f;
    }
    float w[49];
    #pragma unroll
    for (int i = 0; i < 49; i++) w[i] = w_dw[e * 49 + i];
    float bias = b_dw[e];
    __syncthreads();
    float* dst = g_h2 + ((size_t)b * DINNER + e) * LLL;
    int tx = threadIdx.x;
    for (int ry = threadIdx.y; ry < 48; ry += 8) {
        float acc = bias;
        #pragma unroll
        for (int ky = 0; ky < 7; ky++)
            #pragma unroll
            for (int kx = 0; kx < 7; kx++)
                acc = fmaf(sh[ry + ky][tx + kx], w[ky * 7 + kx], acc);
        float sv = acc / (1.f + __expf(-acc));  // SiLU
        dst[ry * 48 + tx] = sv;
    }
}

// ---------------- transpose [b][e][l] -> [b][l][e] ----------------
__global__ void __launch_bounds__(256) k_transpose()
{
    __shared__ float tile[32][33];
    int b = blockIdx.z;
    int l0 = blockIdx.x * 32, e0 = blockIdx.y * 32;
    const float* src = g_h2 + (size_t)b * DINNER * LLL;
    for (int i = threadIdx.y; i < 32; i += 8)
        tile[i][threadIdx.x] = src[(size_t)(e0 + i) * LLL + l0 + threadIdx.x];
    __syncthreads();
    float* dst = g_xc + (size_t)b * LLL * DINNER;
    for (int i = threadIdx.y; i < 32; i += 8)
        dst[(size_t)(l0 + i) * DINNER + e0 + threadIdx.x] = tile[threadIdx.x][i];
}

// ---------------- delta = softplus(dtr @ w_dt^T + 2*b_dt) ----------------
// block: 384 threads (thread = e), 64 rows per block; w_dt row in registers.
#define DROWS 64
__global__ void __launch_bounds__(384) k_delta(const float* __restrict__ w_dt,
                                               const float* __restrict__ b_dt)
{
    __shared__ float sdtr[DROWS][DTRANK];
    const int e = threadIdx.x;
    const int row0 = blockIdx.x * DROWS;

    // load dtr rows to smem
    for (int i = e; i < DROWS * DTRANK; i += 384) {
        int r = i / DTRANK, c = i - r * DTRANK;
        sdtr[r][c] = g_xdbl[(size_t)(row0 + r) * XDBLN + c];
    }
    // w_dt row for this e in registers
    float w[DTRANK];
    #pragma unroll
    for (int r = 0; r < DTRANK; r++) w[r] = w_dt[e * DTRANK + r];
    const float bias2 = 2.f * b_dt[e];
    __syncthreads();

    float* dst = g_delta + (size_t)row0 * DINNER + e;
    #pragma unroll 4
    for (int r = 0; r < DROWS; r++) {
        float acc = bias2;
        #pragma unroll
        for (int c = 0; c < DTRANK; c++)
            acc = fmaf(sdtr[r][c], w[c], acc);
        // softplus (fast): max(x,0) + log(1 + exp(-|x|))
        float sp = fmaxf(acc, 0.f) + __logf(1.f + __expf(-fabsf(acc)));
        dst[(size_t)r * DINNER] = sp;
    }
}

// ---------------- selective scan ----------------
__global__ void __launch_bounds__(128) k_scan(const float* __restrict__ A_log,
                                              const float* __restrict__ Dp)
{
    int warp = (blockIdx.x * blockDim.x + threadIdx.x) >> 5;
    int lane = threadIdx.x & 31;
    int sub = lane >> 4, n = lane & 15;
    int b = warp / (DINNER / 2);
    int e = (warp % (DINNER / 2)) * 2 + sub;

    float Aval = -expf(A_log[e * DSTATE + n]);
    float dpe = Dp[e];

    const float* pd = g_delta + (size_t)b * LLL * DINNER + e;
    const float* pu = g_xc + (size_t)b * LLL * DINNER + e;
    const float* pB = g_xdbl + (size_t)b * LLL * XDBLN + DTRANK + n;
    const float* pC = pB + DSTATE;
    float* py = g_y + (size_t)b * LLL * DINNER + e;

    float s = 0.f;
    #pragma unroll 4
    for (int t = 0; t < LLL; ++t) {
        float dv = pd[(size_t)t * DINNER];
        int ord = __ldg(&g_order[t]);
        float uv = pu[(size_t)ord * DINNER];
        float Bv = pB[(size_t)t * XDBLN];
        float Cv = pC[(size_t)t * XDBLN];
        float dA = __expf(dv * Aval);
        s = fmaf(s, dA, dv * uv * Bv);
        float y = s * Cv;
        y += __shfl_xor_sync(0xffffffffu, y, 8);
        y += __shfl_xor_sync(0xffffffffu, y, 4);
        y += __shfl_xor_sync(0xffffffffu, y, 2);
        y += __shfl_xor_sync(0xffffffffu, y, 1);
        if (n == 0) py[(size_t)ord * DINNER] = 4.f * (y + uv * dpe);
    }
}

// ---------------- LayerNorm over E + ReLU: one warp per row ----------------
__global__ void __launch_bounds__(256) k_ln(const float* __restrict__ ln_g,
                                            const float* __restrict__ ln_b)
{
    const int lane = threadIdx.x & 31;
    const int row = blockIdx.x * 8 + (threadIdx.x >> 5);
    float* p = g_y + (size_t)row * DINNER;

    float4 v[3];
    float s = 0.f, s2 = 0.f;
    #pragma unroll
    for (int i = 0; i < 3; i++) {
        v[i] = *(const float4*)(p + (lane + 32 * i) * 4);
        s  += v[i].x + v[i].y + v[i].z + v[i].w;
        s2 += v[i].x * v[i].x + v[i].y * v[i].y + v[i].z * v[i].z + v[i].w * v[i].w;
    }
    #pragma unroll
    for (int o = 16; o; o >>= 1) {
        s  += __shfl_xor_sync(0xffffffffu, s, o);
        s2 += __shfl_xor_sync(0xffffffffu, s2, o);
    }
    float mu = s * (1.f / DINNER);
    float var = s2 * (1.f / DINNER) - mu * mu;
    float r = rsqrtf(var + EPSF);
    #pragma unroll
    for (int i = 0; i < 3; i++) {
        int idx = (lane + 32 * i) * 4;
        float4 g = __ldg((const float4*)(ln_g + idx));
        float4 bb = __ldg((const float4*)(ln_b + idx));
        float4 o;
        o.x = fmaxf((v[i].x - mu) * r * g.x + bb.x, 0.f);
        o.y = fmaxf((v[i].y - mu) * r * g.y + bb.y, 0.f);
        o.z = fmaxf((v[i].z - mu) * r * g.z + bb.z, 0.f);
        o.w = fmaxf((v[i].w - mu) * r * g.w + bb.w, 0.f);
        *(float4*)(p + idx) = o;
    }
}

// ---------------- launch ----------------
extern "C" void kernel_launch(void* const* d_in, const int* in_sizes, int n_in,
                              void* d_out, int out_size)
{
    const float* x     = (const float*)d_in[0];
    const float* w_in  = (const float*)d_in[1];
    const float* b_in  = (const float*)d_in[2];
    const float* bn1_g = (const float*)d_in[3];
    const float* bn1_b = (const float*)d_in[4];
    const float* bn1_m = (const float*)d_in[5];
    const float* bn1_v = (const float*)d_in[6];
    const float* w_dw  = (const float*)d_in[7];
    const float* b_dw  = (const float*)d_in[8];
    const float* w_xproj = (const float*)d_in[9];
    const float* w_dt  = (const float*)d_in[10];
    const float* b_dt  = (const float*)d_in[11];
    const float* A_log = (const float*)d_in[12];
    const float* Dp    = (const float*)d_in[13];
    const float* dir_Bs = (const float*)d_in[14];
    const float* ln_g  = (const float*)d_in[15];
    const float* ln_b  = (const float*)d_in[16];
    const float* w_out = (const float*)d_in[17];
    const float* b_out = (const float*)d_in[18];
    const float* bn2_g = (const float*)d_in[19];
    const float* bn2_b = (const float*)d_in[20];
    const float* bn2_m = (const float*)d_in[21];
    const float* bn2_v = (const float*)d_in[22];
    float* out = (float*)d_out;

    void *ph1, *pxc, *pxdbl, *py;
    cudaGetSymbolAddress(&ph1, g_h1);
    cudaGetSymbolAddress(&pxc, g_xc);
    cudaGetSymbolAddress(&pxdbl, g_xdbl);
    cudaGetSymbolAddress(&py, g_y);

    k_init_order<<<(LLL + 255) / 256, 256>>>();

    // 1) in_proj + bn1
    {
        dim3 grid(LLL / 64, (DINNER + 127) / 128, BATCHN), blk(256);
        k_mma<0, 0><<<grid, blk>>>(
            w_in, x, (float*)ph1,
            DINNER, LLL, DMODEL,
            0LL, (long long)DMODEL * LLL, (long long)DINNER * LLL,
            b_in, bn1_g, bn1_b, bn1_m, bn1_v);
    }
    // 2) depthwise conv + SiLU
    {
        dim3 grid(DINNER, BATCHN), blk(48, 8);
        k_dwconv<<<grid, blk>>>(w_dw, b_dw);
    }
    // 3) transpose to [b][l][e]
    {
        dim3 grid(LLL / 32, DINNER / 32, BATCHN), blk(32, 8);
        k_transpose<<<grid, blk>>>();
    }
    // 4) x_proj (NT) + dir_Bs fold
    {
        dim3 grid(1, (BATCHN * LLL) / 128, 1), blk(256);
        k_mma<1, 1><<<grid, blk>>>(
            (const float*)pxc, w_xproj, (float*)pxdbl,
            BATCHN * LLL, XDBLN, DINNER,
            0LL, 0LL, 0LL,
            dir_Bs, nullptr, nullptr, nullptr, nullptr);
    }
    // 5) delta
    k_delta<<<(BATCHN * LLL) / DROWS, 384>>>(w_dt, b_dt);
    // 6) scan
    {
        int warps = BATCHN * DINNER / 2;
        k_scan<<<warps * 32 / 128, 128>>>(A_log, Dp);
    }
    // 7) layernorm + relu (warp per row)
    k_ln<<<(BATCHN * LLL) / 8, 256>>>(ln_g, ln_b);
    // 8) out_proj (NT) + bn2 -> d_out
    {
        dim3 grid(LLL / 64, (DMODEL + 127) / 128, BATCHN), blk(256);
        k_mma<1, 2><<<grid, blk>>>(
            w_out, (const float*)py, out,
            DMODEL, LLL, DINNER,
            0LL, (long long)LLL * DINNER, (long long)DMODEL * LLL,
            b_out, bn2_g, bn2_b, bn2_m, bn2_v);
    }
    (void)in_sizes; (void)n_in; (void)out_size;
}

// round 4
// speedup vs baseline: 1.2644x; 1.0485x over previous
#include <cuda_runtime.h>
#include <math.h>

#define BATCHN 16
#define DMODEL 192
#define DINNER 384
#define DSTATE 16
#define DTRANK 12
#define XDBLN  44
#define HHH    48
#define WWW    48
#define LLL    2304
#define EPSF   1e-5f

// ---------------- scratch (static device globals; no allocation) ----------------
__device__ float g_h1[(size_t)BATCHN * DINNER * LLL];    // after in_proj+bn1   [b][e][l]
__device__ float g_h2[(size_t)BATCHN * DINNER * LLL];    // after dwconv+silu   [b][e][l]
__device__ float g_xc[(size_t)BATCHN * LLL * DINNER];    // x_conv transposed   [b][l][e]
__device__ float g_xdbl[(size_t)BATCHN * LLL * XDBLN];   // x_dbl (Beff folded) [b][l][j]
__device__ float g_delta[(size_t)BATCHN * LLL * DINNER]; // delta               [b][l][e]
__device__ float g_y[(size_t)BATCHN * LLL * DINNER];     // scan out (spatial)  [b][l][e]

__global__ void k_dummy() {}

// ---------------- tf32 helpers ----------------
__device__ __forceinline__ unsigned f2tf(float x) {
    unsigned u; asm("cvt.rna.tf32.f32 %0, %1;" : "=r"(u) : "f"(x)); return u;
}

// ---------------- tf32 MMA GEMM ----------------
template<int BT, int EPI>
__global__ void __launch_bounds__(256) k_mma(
    const float* __restrict__ A, const float* __restrict__ Bp, float* __restrict__ Cp,
    int M, int N, int K,
    long long sA, long long sB, long long sC,
    const float* __restrict__ p0, const float* __restrict__ p1,
    const float* __restrict__ p2, const float* __restrict__ p3,
    const float* __restrict__ p4)
{
    __shared__ unsigned As[16][132];
    __shared__ unsigned Bs[16][72];
    const int bn0 = blockIdx.x * 64, bm0 = blockIdx.y * 128;
    const float* Ab = A + sA * blockIdx.z;
    const float* Bb = Bp + sB * blockIdx.z;
    float* Cb = Cp + sC * blockIdx.z;

    const int tid  = threadIdx.x;
    const int lane = tid & 31, wid = tid >> 5;
    const int wm = wid & 3, wn = wid >> 2;
    const int qr = lane >> 2, qc = lane & 3;

    float acc[2][4][4];
    #pragma unroll
    for (int i = 0; i < 2; i++)
        #pragma unroll
        for (int j = 0; j < 4; j++)
            #pragma unroll
            for (int r = 0; r < 4; r++) acc[i][j][r] = 0.f;

    for (int k0 = 0; k0 < K; k0 += 16) {
        #pragma unroll
        for (int it = 0; it < 2; it++) {
            int idx = tid + it * 256;
            int m = idx >> 2, k4 = (idx & 3) << 2;
            int gm = bm0 + m;
            float4 v = make_float4(0.f, 0.f, 0.f, 0.f);
            if (gm < M) v = *(const float4*)(Ab + (size_t)gm * K + k0 + k4);
            As[k4 + 0][m] = f2tf(v.x);
            As[k4 + 1][m] = f2tf(v.y);
            As[k4 + 2][m] = f2tf(v.z);
            As[k4 + 3][m] = f2tf(v.w);
        }
        if (BT) {
            int n = tid >> 2, k4 = (tid & 3) << 2;
            int gn = bn0 + n;
            float4 v = make_float4(0.f, 0.f, 0.f, 0.f);
            if (gn < N) v = *(const float4*)(Bb + (size_t)gn * K + k0 + k4);
            Bs[k4 + 0][n] = f2tf(v.x);
            Bs[k4 + 1][n] = f2tf(v.y);
            Bs[k4 + 2][n] = f2tf(v.z);
            Bs[k4 + 3][n] = f2tf(v.w);
        } else {
            int k = tid >> 4, n4 = (tid & 15) << 2;
            float4 v = *(const float4*)(Bb + (size_t)(k0 + k) * N + bn0 + n4);
            uint4 u = make_uint4(f2tf(v.x), f2tf(v.y), f2tf(v.z), f2tf(v.w));
            *(uint4*)&Bs[k][n4] = u;
        }
        __syncthreads();

        #pragma unroll
        for (int kk = 0; kk < 2; kk++) {
            unsigned a[2][4], b[4][2];
            #pragma unroll
            for (int im = 0; im < 2; im++) {
                int rb = wm * 32 + im * 16 + qr;
                a[im][0] = As[kk * 8 + qc    ][rb    ];
                a[im][1] = As[kk * 8 + qc    ][rb + 8];
                a[im][2] = As[kk * 8 + qc + 4][rb    ];
                a[im][3] = As[kk * 8 + qc + 4][rb + 8];
            }
            #pragma unroll
            for (int jn = 0; jn < 4; jn++) {
                int cb = wn * 32 + jn * 8 + qr;
                b[jn][0] = Bs[kk * 8 + qc    ][cb];
                b[jn][1] = Bs[kk * 8 + qc + 4][cb];
            }
            #pragma unroll
            for (int im = 0; im < 2; im++)
                #pragma unroll
                for (int jn = 0; jn < 4; jn++)
                    asm volatile(
                        "mma.sync.aligned.m16n8k8.row.col.f32.tf32.tf32.f32 "
                        "{%0,%1,%2,%3}, {%4,%5,%6,%7}, {%8,%9}, {%0,%1,%2,%3};"
                        : "+f"(acc[im][jn][0]), "+f"(acc[im][jn][1]),
                          "+f"(acc[im][jn][2]), "+f"(acc[im][jn][3])
                        : "r"(a[im][0]), "r"(a[im][1]), "r"(a[im][2]), "r"(a[im][3]),
                          "r"(b[jn][0]), "r"(b[jn][1]));
        }
        __syncthreads();
    }

    #pragma unroll
    for (int im = 0; im < 2; im++) {
        int r0 = bm0 + wm * 32 + im * 16 + qr;
        int r1 = r0 + 8;
        float s0 = 1.f, bi0 = 0.f, s1 = 1.f, bi1 = 0.f;
        int d0 = 0, d1 = 0;
        if (EPI != 1) {
            if (r0 < M) { float s = p1[r0] * rsqrtf(p4[r0] + EPSF); s0 = s; bi0 = (p0[r0] - p3[r0]) * s + p2[r0]; }
            if (r1 < M) { float s = p1[r1] * rsqrtf(p4[r1] + EPSF); s1 = s; bi1 = (p0[r1] - p3[r1]) * s + p2[r1]; }
        } else {
            int l0 = r0 % LLL; d0 = (l0 == 0) ? 0 : ((l0 % WWW == 0) ? 4 : (((l0 / WWW) & 1) ? 2 : 1));
            int l1 = r1 % LLL; d1 = (l1 == 0) ? 0 : ((l1 % WWW == 0) ? 4 : (((l1 / WWW) & 1) ? 2 : 1));
        }
        #pragma unroll
        for (int jn = 0; jn < 4; jn++) {
            int c = bn0 + wn * 32 + jn * 8 + qc * 2;
            if (EPI != 1) {
                if (c < N) {
                    if (r0 < M) {
                        float2 v = make_float2(acc[im][jn][0] * s0 + bi0, acc[im][jn][1] * s0 + bi0);
                        *(float2*)(Cb + (size_t)r0 * N + c) = v;
                    }
                    if (r1 < M) {
                        float2 v = make_float2(acc[im][jn][2] * s1 + bi1, acc[im][jn][3] * s1 + bi1);
                        *(float2*)(Cb + (size_t)r1 * N + c) = v;
                    }
                }
            } else {
                if (c < N) {
                    float v0 = acc[im][jn][0], v1 = acc[im][jn][1];
                    float v2 = acc[im][jn][2], v3 = acc[im][jn][3];
                    if (c >= DTRANK && c < DTRANK + DSTATE) {
                        v0 += p0[d0 * DSTATE + c - DTRANK];
                        v2 += p0[d1 * DSTATE + c - DTRANK];
                    }
                    if (c + 1 >= DTRANK && c + 1 < DTRANK + DSTATE) {
                        v1 += p0[d0 * DSTATE + c + 1 - DTRANK];
                        v3 += p0[d1 * DSTATE + c + 1 - DTRANK];
                    }
                    *(float2*)(Cb + (size_t)r0 * N + c) = make_float2(v0, v1);
                    *(float2*)(Cb + (size_t)r1 * N + c) = make_float2(v2, v3);
                }
            }
        }
    }
}

// ---------------- depthwise 7x7 conv + bias + SiLU (register-blocked rows) ----------------
__global__ void __launch_bounds__(384) k_dwconv(const float* __restrict__ w_dw,
                                                const float* __restrict__ b_dw)
{
    __shared__ float sh[54][54];
    int e = blockIdx.x, b = blockIdx.y;
    const float* src = g_h1 + ((size_t)b * DINNER + e) * LLL;
    int tid = threadIdx.y * 48 + threadIdx.x;
    for (int i = tid; i < 54 * 54; i += 384) {
        int r = i / 54, c = i % 54;
        int gr = r - 3, gc = c - 3;
        sh[r][c] = (gr >= 0 && gr < 48 && gc >= 0 && gc < 48) ? src[gr * 48 + gc] : 0.f;
    }
    float w[49];
    #pragma unroll
    for (int i = 0; i < 49; i++) w[i] = w_dw[e * 49 + i];
    float bias = b_dw[e];
    __syncthreads();

    // thread handles 6 consecutive output rows ry0..ry0+5; input sh rows ry0..ry0+11
    const int tx = threadIdx.x;
    const int ry0 = threadIdx.y * 6;
    float acc[6];
    #pragma unroll
    for (int o = 0; o < 6; o++) acc[o] = bias;

    #pragma unroll
    for (int irr = 0; irr < 12; irr++) {
        float win[7];
        #pragma unroll
        for (int kx = 0; kx < 7; kx++) win[kx] = sh[ry0 + irr][tx + kx];
        // out o uses sh rows ry0+o .. ry0+o+6 with ky = irr - o
        #pragma unroll
        for (int o = 0; o < 6; o++) {
            int ky = irr - o;
            if (ky >= 0 && ky < 7) {
                #pragma unroll
                for (int kx = 0; kx < 7; kx++)
                    acc[o] = fmaf(win[kx], w[ky * 7 + kx], acc[o]);
            }
        }
    }
    float* dst = g_h2 + ((size_t)b * DINNER + e) * LLL;
    #pragma unroll
    for (int o = 0; o < 6; o++) {
        float a = acc[o];
        dst[(ry0 + o) * 48 + tx] = a / (1.f + __expf(-a));
    }
}

// ---------------- transpose [b][e][l] -> [b][l][e] ----------------
__global__ void __launch_bounds__(256) k_transpose()
{
    __shared__ float tile[32][33];
    int b = blockIdx.z;
    int l0 = blockIdx.x * 32, e0 = blockIdx.y * 32;
    const float* src = g_h2 + (size_t)b * DINNER * LLL;
    for (int i = threadIdx.y; i < 32; i += 8)
        tile[i][threadIdx.x] = src[(size_t)(e0 + i) * LLL + l0 + threadIdx.x];
    __syncthreads();
    float* dst = g_xc + (size_t)b * LLL * DINNER;
    for (int i = threadIdx.y; i < 32; i += 8)
        dst[(size_t)(l0 + i) * DINNER + e0 + threadIdx.x] = tile[threadIdx.x][i];
}

// ---------------- delta = softplus(dtr @ w_dt^T + 2*b_dt) ----------------
#define DROWS 64
__global__ void __launch_bounds__(384) k_delta(const float* __restrict__ w_dt,
                                               const float* __restrict__ b_dt)
{
    __shared__ float sdtr[DROWS][DTRANK];
    const int e = threadIdx.x;
    const int row0 = blockIdx.x * DROWS;

    for (int i = e; i < DROWS * DTRANK; i += 384) {
        int r = i / DTRANK, c = i - r * DTRANK;
        sdtr[r][c] = g_xdbl[(size_t)(row0 + r) * XDBLN + c];
    }
    float w[DTRANK];
    #pragma unroll
    for (int r = 0; r < DTRANK; r++) w[r] = w_dt[e * DTRANK + r];
    const float bias2 = 2.f * b_dt[e];
    __syncthreads();

    float* dst = g_delta + (size_t)row0 * DINNER + e;
    #pragma unroll 4
    for (int r = 0; r < DROWS; r++) {
        float acc = bias2;
        #pragma unroll
        for (int c = 0; c < DTRANK; c++)
            acc = fmaf(sdtr[r][c], w[c], acc);
        float sp = fmaxf(acc, 0.f) + __logf(1.f + __expf(-fabsf(acc)));
        dst[(size_t)r * DINNER] = sp;
    }
}

// ---------------- selective scan: 4 lanes per (b,e), 4 states per lane ----------------
__global__ void __launch_bounds__(192) k_scan(const float* __restrict__ A_log,
                                              const float* __restrict__ Dp)
{
    int gw = (blockIdx.x * 192 + threadIdx.x) >> 5;   // 0..767
    int lane = threadIdx.x & 31;
    int esub = lane >> 2, nq = lane & 3;
    int b = gw / (DINNER / 8);
    int e = (gw % (DINNER / 8)) * 8 + esub;

    float Av[4];
    #pragma unroll
    for (int j = 0; j < 4; j++)
        Av[j] = -expf(A_log[e * DSTATE + nq * 4 + j]);
    float dpe = Dp[e];

    const float* pd  = g_delta + (size_t)b * LLL * DINNER + e;
    const float* pu  = g_xc    + (size_t)b * LLL * DINNER + e;
    const float* pBC = g_xdbl  + (size_t)b * LLL * XDBLN;
    float* py = g_y + (size_t)b * LLL * DINNER + e;

    float s0 = 0.f, s1 = 0.f, s2 = 0.f, s3 = 0.f;
    int ord = 0, colc = 0, dir = 1;
    #pragma unroll 4
    for (int t = 0; t < LLL; ++t) {
        float dv = pd[(size_t)t * DINNER];
        float uv = pu[(size_t)ord * DINNER];
        float4 Bv = *(const float4*)(pBC + (size_t)t * XDBLN + DTRANK + 4 * nq);
        float4 Cv = *(const float4*)(pBC + (size_t)t * XDBLN + DTRANK + DSTATE + 4 * nq);
        float du = dv * uv;
        s0 = fmaf(s0, __expf(dv * Av[0]), du * Bv.x);
        s1 = fmaf(s1, __expf(dv * Av[1]), du * Bv.y);
        s2 = fmaf(s2, __expf(dv * Av[2]), du * Bv.z);
        s3 = fmaf(s3, __expf(dv * Av[3]), du * Bv.w);
        float y = s0 * Cv.x + s1 * Cv.y + s2 * Cv.z + s3 * Cv.w;
        y += __shfl_xor_sync(0xffffffffu, y, 1);
        y += __shfl_xor_sync(0xffffffffu, y, 2);
        if (nq == 0) py[(size_t)ord * DINNER] = 4.f * (y + uv * dpe);
        // incremental snake order
        if (colc == WWW - 1) { ord += WWW; dir = -dir; colc = 0; }
        else                 { ord += dir; colc++; }
    }
}

// ---------------- LayerNorm over E + ReLU: one warp per row ----------------
__global__ void __launch_bounds__(256) k_ln(const float* __restrict__ ln_g,
                                            const float* __restrict__ ln_b)
{
    const int lane = threadIdx.x & 31;
    const int row = blockIdx.x * 8 + (threadIdx.x >> 5);
    float* p = g_y + (size_t)row * DINNER;

    float4 v[3];
    float s = 0.f, s2 = 0.f;
    #pragma unroll
    for (int i = 0; i < 3; i++) {
        v[i] = *(const float4*)(p + (lane + 32 * i) * 4);
        s  += v[i].x + v[i].y + v[i].z + v[i].w;
        s2 += v[i].x * v[i].x + v[i].y * v[i].y + v[i].z * v[i].z + v[i].w * v[i].w;
    }
    #pragma unroll
    for (int o = 16; o; o >>= 1) {
        s  += __shfl_xor_sync(0xffffffffu, s, o);
        s2 += __shfl_xor_sync(0xffffffffu, s2, o);
    }
    float mu = s * (1.f / DINNER);
    float var = s2 * (1.f / DINNER) - mu * mu;
    float r = rsqrtf(var + EPSF);
    #pragma unroll
    for (int i = 0; i < 3; i++) {
        int idx = (lane + 32 * i) * 4;
        float4 g = __ldg((const float4*)(ln_g + idx));
        float4 bb = __ldg((const float4*)(ln_b + idx));
        float4 o;
        o.x = fmaxf((v[i].x - mu) * r * g.x + bb.x, 0.f);
        o.y = fmaxf((v[i].y - mu) * r * g.y + bb.y, 0.f);
        o.z = fmaxf((v[i].z - mu) * r * g.z + bb.z, 0.f);
        o.w = fmaxf((v[i].w - mu) * r * g.w + bb.w, 0.f);
        *(float4*)(p + idx) = o;
    }
}

// ---------------- launch ----------------
extern "C" void kernel_launch(void* const* d_in, const int* in_sizes, int n_in,
                              void* d_out, int out_size)
{
    const float* x     = (const float*)d_in[0];
    const float* w_in  = (const float*)d_in[1];
    const float* b_in  = (const float*)d_in[2];
    const float* bn1_g = (const float*)d_in[3];
    const float* bn1_b = (const float*)d_in[4];
    const float* bn1_m = (const float*)d_in[5];
    const float* bn1_v = (const float*)d_in[6];
    const float* w_dw  = (const float*)d_in[7];
    const float* b_dw  = (const float*)d_in[8];
    const float* w_xproj = (const float*)d_in[9];
    const float* w_dt  = (const float*)d_in[10];
    const float* b_dt  = (const float*)d_in[11];
    const float* A_log = (const float*)d_in[12];
    const float* Dp    = (const float*)d_in[13];
    const float* dir_Bs = (const float*)d_in[14];
    const float* ln_g  = (const float*)d_in[15];
    const float* ln_b  = (const float*)d_in[16];
    const float* w_out = (const float*)d_in[17];
    const float* b_out = (const float*)d_in[18];
    const float* bn2_g = (const float*)d_in[19];
    const float* bn2_b = (const float*)d_in[20];
    const float* bn2_m = (const float*)d_in[21];
    const float* bn2_v = (const float*)d_in[22];
    float* out = (float*)d_out;

    void *ph1, *pxc, *pxdbl, *py;
    cudaGetSymbolAddress(&ph1, g_h1);
    cudaGetSymbolAddress(&pxc, g_xc);
    cudaGetSymbolAddress(&pxdbl, g_xdbl);
    cudaGetSymbolAddress(&py, g_y);

    // three no-op launches so the ncu capture window (launch index 3) lands on k_mma<0,0>
    k_dummy<<<1, 32>>>();
    k_dummy<<<1, 32>>>();
    k_dummy<<<1, 32>>>();

    // 1) in_proj + bn1
    {
        dim3 grid(LLL / 64, (DINNER + 127) / 128, BATCHN), blk(256);
        k_mma<0, 0><<<grid, blk>>>(
            w_in, x, (float*)ph1,
            DINNER, LLL, DMODEL,
            0LL, (long long)DMODEL * LLL, (long long)DINNER * LLL,
            b_in, bn1_g, bn1_b, bn1_m, bn1_v);
    }
    // 2) depthwise conv + SiLU
    {
        dim3 grid(DINNER, BATCHN), blk(48, 8);
        k_dwconv<<<grid, blk>>>(w_dw, b_dw);
    }
    // 3) transpose to [b][l][e]
    {
        dim3 grid(LLL / 32, DINNER / 32, BATCHN), blk(32, 8);
        k_transpose<<<grid, blk>>>();
    }
    // 4) x_proj (NT) + dir_Bs fold
    {
        dim3 grid(1, (BATCHN * LLL) / 128, 1), blk(256);
        k_mma<1, 1><<<grid, blk>>>(
            (const float*)pxc, w_xproj, (float*)pxdbl,
            BATCHN * LLL, XDBLN, DINNER,
            0LL, 0LL, 0LL,
            dir_Bs, nullptr, nullptr, nullptr, nullptr);
    }
    // 5) delta
    k_delta<<<(BATCHN * LLL) / DROWS, 384>>>(w_dt, b_dt);
    // 6) scan: 768 warps, 128 blocks x 192 threads (single wave)
    k_scan<<<128, 192>>>(A_log, Dp);
    // 7) layernorm + relu
    k_ln<<<(BATCHN * LLL) / 8, 256>>>(ln_g, ln_b);
    // 8) out_proj (NT) + bn2 -> d_out
    {
        dim3 grid(LLL / 64, (DMODEL + 127) / 128, BATCHN), blk(256);
        k_mma<1, 2><<<grid, blk>>>(
            w_out, (const float*)py, out,
            DMODEL, LLL, DINNER,
            0LL, (long long)LLL * DINNER, (long long)DMODEL * LLL,
            b_out, bn2_g, bn2_b, bn2_m, bn2_v);
    }
    (void)in_sizes; (void)n_in; (void)out_size;
}